// round 7
// baseline (speedup 1.0000x reference)
#include <cuda_runtime.h>
#include <cstdint>

#define B_   16
#define N_   1024
#define M_   12
#define FB_  32
#define F_   128
#define ROWS_TOT (B_ * N_)   // 16384

__device__ float g_p[ROWS_TOT];
__device__ float g_s[ROWS_TOT];
__device__ float g_Y[ROWS_TOT * F_];   // unscaled GEMM result (8 MB)

static __device__ __forceinline__ uint32_t s2u(const void* p) {
    return (uint32_t)__cvta_generic_to_shared(p);
}

// ---------------------------------------------------------------------------
// Kernel A: bond prologue + gather + GEMM -> Y (no s/bias/relu).
//   256 blocks x 256 threads, 64 rows each. smem: sA2 64KB (dup pairs) + sW 16KB.
//   Microtile: 4 rows x 8 cols, col-pair packed fma.rn.f32x2.
// ---------------------------------------------------------------------------
extern __shared__ float dsm[];

__global__ __launch_bounds__(256) void fused_kernel(
    const float* __restrict__ atom, const int* __restrict__ adj,
    const float* __restrict__ bond, const float* __restrict__ W)
{
    float2* sA2 = (float2*)dsm;            // [64 rows][128 k] as (a,a)
    float*  sW  = dsm + 2 * 64 * F_;       // [32 k][128 c]

    int tid  = threadIdx.x;
    int wid  = tid >> 5;
    int lane = tid & 31;
    int row0 = blockIdx.x << 6;

    // ================= Bond prologue: this block's 64 rows ================
    {
        int grp = lane >> 3;       // m within quartet
        int sub = lane & 7;        // float4 slot within FB=32
#pragma unroll
        for (int q = 0; q < 2; ++q) {
            int r0 = row0 + (wid << 3) + (q << 2);     // 4-row quartet
            const float* b = bond + (size_t)r0 * (M_ * FB_);
            float4 v[4][3];
#pragma unroll
            for (int j = 0; j < 4; ++j)
#pragma unroll
                for (int i = 0; i < 3; ++i)
                    v[j][i] = *(const float4*)(b + j * (M_ * FB_)
                                                 + ((((i << 2) + grp) << 5) + (sub << 2)));
            float sum[4], prod[4];
#pragma unroll
            for (int j = 0; j < 4; ++j) { sum[j] = 0.f; prod[j] = 1.f; }
#pragma unroll
            for (int i = 0; i < 3; ++i) {
                float s[4];
#pragma unroll
                for (int j = 0; j < 4; ++j) {
                    float4 u = v[j][i];
                    s[j] = u.x*u.x + u.y*u.y + u.z*u.z + u.w*u.w;
                }
#pragma unroll
                for (int off = 1; off <= 4; off <<= 1)
#pragma unroll
                    for (int j = 0; j < 4; ++j)
                        s[j] += __shfl_xor_sync(0xffffffffu, s[j], off);
#pragma unroll
                for (int j = 0; j < 4; ++j) {
                    float r = 1.0f / s[j];     // (sqrt(s))^-2 == 1/s
                    sum[j] += r; prod[j] *= r;
                }
            }
#pragma unroll
            for (int off = 8; off <= 16; off <<= 1)
#pragma unroll
                for (int j = 0; j < 4; ++j) {
                    sum[j]  += __shfl_xor_sync(0xffffffffu, sum[j], off);
                    prod[j] *= __shfl_xor_sync(0xffffffffu, prod[j], off);
                }
            if (lane < 4) {
                float S = (lane == 0) ? sum[0]  : (lane == 1) ? sum[1]  : (lane == 2) ? sum[2]  : sum[3];
                float P = (lane == 0) ? prod[0] : (lane == 1) ? prod[1] : (lane == 2) ? prod[2] : prod[3];
                float D = fmaxf(S, 1e-12f);
                float d2 = D * D, d4 = d2 * d2;
                g_p[r0 + lane] = P / (d4 * d4 * d4);
            }
        }
    }

    // ================= Build A tile (gather + mean), duplicated pairs =====
#pragma unroll
    for (int rr = 0; rr < 8; ++rr) {
        int r = (wid << 3) + rr;
        int g = row0 + r;
        int b = g >> 10;
        const float* arow  = atom + ((size_t)g << 7);
        const float* abase = atom + ((size_t)b << 17);
        int myidx = (lane < M_) ? adj[(size_t)g * M_ + lane] : 0;

        float4 self = *(const float4*)(arow + (lane << 2));
        float ax = 0.f, ay = 0.f, az = 0.f, aw = 0.f;
#pragma unroll
        for (int m = 0; m < M_; ++m) {
            int idx = __shfl_sync(0xffffffffu, myidx, m) & (N_ - 1);
            float4 nb = *(const float4*)(abase + ((size_t)idx << 7) + (lane << 2));
            ax += nb.x; ay += nb.y; az += nb.z; aw += nb.w;
        }
        const float inv12 = 1.0f / 12.0f;
        float vx = self.x + ax * inv12;
        float vy = self.y + ay * inv12;
        float vz = self.z + az * inv12;
        float vw = self.w + aw * inv12;
        float4* dst = (float4*)&sA2[r * F_ + (lane << 2)];
        dst[0] = make_float4(vx, vx, vy, vy);
        dst[1] = make_float4(vz, vz, vw, vw);
    }

    // ================= GEMM mainloop ======================================
    // lane>>4 : row-quad (0..1), lane&15 : col-octet (0..15)
    uint64_t acc[4][4];
#pragma unroll
    for (int r = 0; r < 4; ++r)
#pragma unroll
        for (int j = 0; j < 4; ++j) acc[r][j] = 0ull;

    uint32_t a_base = s2u(sA2) + (uint32_t)(((wid << 3) + ((lane >> 4) << 2)) * F_) * 8u;
    uint32_t w_base = s2u(sW) + ((uint32_t)(lane & 15) << 5);

#pragma unroll
    for (int kc = 0; kc < 4; ++kc) {
        __syncthreads();   // protects sW (and sA2 build on kc==0)
        {
            const float4* src = (const float4*)(W + (size_t)(kc << 5) * F_);
            float4* dstw = (float4*)sW;
#pragma unroll
            for (int t = 0; t < 4; ++t) dstw[tid + (t << 8)] = src[tid + (t << 8)];
        }
        __syncthreads();

        uint32_t kb8 = (uint32_t)(kc << 5) * 8u;
#pragma unroll 4
        for (int kk = 0; kk < 32; ++kk) {
            uint64_t w01, w23, w45, w67;
            asm("ld.shared.v2.u64 {%0,%1}, [%2];"
                : "=l"(w01), "=l"(w23) : "r"(w_base + (uint32_t)(kk << 9)));
            asm("ld.shared.v2.u64 {%0,%1}, [%2];"
                : "=l"(w45), "=l"(w67) : "r"(w_base + (uint32_t)(kk << 9) + 16u));
#pragma unroll
            for (int r = 0; r < 4; ++r) {
                uint64_t a2;
                asm("ld.shared.u64 %0, [%1];"
                    : "=l"(a2) : "r"(a_base + (uint32_t)(r * F_ * 8) + kb8 + (uint32_t)(kk << 3)));
                asm("fma.rn.f32x2 %0, %1, %2, %0;" : "+l"(acc[r][0]) : "l"(a2), "l"(w01));
                asm("fma.rn.f32x2 %0, %1, %2, %0;" : "+l"(acc[r][1]) : "l"(a2), "l"(w23));
                asm("fma.rn.f32x2 %0, %1, %2, %0;" : "+l"(acc[r][2]) : "l"(a2), "l"(w45));
                asm("fma.rn.f32x2 %0, %1, %2, %0;" : "+l"(acc[r][3]) : "l"(a2), "l"(w67));
            }
        }
    }

    // ================= Write raw Y ========================================
    int col0 = (lane & 15) << 3;
#pragma unroll
    for (int r = 0; r < 4; ++r) {
        int g = row0 + (wid << 3) + ((lane >> 4) << 2) + r;
        float c0,c1,c2,c3,c4,c5,c6,c7;
        asm("mov.b64 {%0, %1}, %2;" : "=f"(c0), "=f"(c1) : "l"(acc[r][0]));
        asm("mov.b64 {%0, %1}, %2;" : "=f"(c2), "=f"(c3) : "l"(acc[r][1]));
        asm("mov.b64 {%0, %1}, %2;" : "=f"(c4), "=f"(c5) : "l"(acc[r][2]));
        asm("mov.b64 {%0, %1}, %2;" : "=f"(c6), "=f"(c7) : "l"(acc[r][3]));
        float* yrow = g_Y + ((size_t)g << 7) + col0;
        *(float4*)(yrow)     = make_float4(c0, c1, c2, c3);
        *(float4*)(yrow + 4) = make_float4(c4, c5, c6, c7);
    }
}

// ---------------------------------------------------------------------------
// Kernel B: colsum over B, u = max(colsum,eps)/p, s = u / sum_n u
// ---------------------------------------------------------------------------
__global__ void s_kernel() {
    __shared__ float red[32];
    int b = blockIdx.x, n = threadIdx.x;
    int wid = n >> 5, lane = n & 31;

    float cs = 0.f;
#pragma unroll
    for (int bb = 0; bb < B_; ++bb) cs += g_p[bb * N_ + n];
    float u = fmaxf(cs, 1e-12f) / g_p[b * N_ + n];

    float v = u;
#pragma unroll
    for (int off = 16; off; off >>= 1) v += __shfl_xor_sync(0xffffffffu, v, off);
    if (lane == 0) red[wid] = v;
    __syncthreads();
    if (wid == 0) {
        float t = red[lane];
#pragma unroll
        for (int off = 16; off; off >>= 1) t += __shfl_xor_sync(0xffffffffu, t, off);
        if (lane == 0) red[0] = 1.0f / fmaxf(t, 1e-12f);
    }
    __syncthreads();
    g_s[b * N_ + n] = u * red[0];
}

// ---------------------------------------------------------------------------
// Kernel C: epilogue  out = relu(s*Y + bias)
// ---------------------------------------------------------------------------
__global__ __launch_bounds__(256) void epilogue_kernel(
    const float* __restrict__ bias, float* __restrict__ out)
{
    int idx = blockIdx.x * 256 + threadIdx.x;      // float4 index, 524288 total
    int row = idx >> 5;
    int c4  = idx & 31;
    float s = g_s[row];
    float4 y  = *(const float4*)(g_Y + ((size_t)idx << 2));
    float4 bv = *(const float4*)(bias + (c4 << 2));
    float4 o;
    o.x = fmaxf(fmaf(s, y.x, bv.x), 0.f);
    o.y = fmaxf(fmaf(s, y.y, bv.y), 0.f);
    o.z = fmaxf(fmaf(s, y.z, bv.z), 0.f);
    o.w = fmaxf(fmaf(s, y.w, bv.w), 0.f);
    *(float4*)(out + ((size_t)idx << 2)) = o;
}

// ---------------------------------------------------------------------------
extern "C" void kernel_launch(void* const* d_in, const int* in_sizes, int n_in,
                              void* d_out, int out_size) {
    const float* atom = (const float*)d_in[0];
    const float* bond = (const float*)d_in[1];
    const int*   adj  = (const int*)d_in[2];
    const float* W    = (const float*)d_in[3];
    const float* bias = (const float*)d_in[4];
    float*       out  = (float*)d_out;

    static bool attr_done = false;
    if (!attr_done) {
        cudaFuncSetAttribute(fused_kernel,
                             cudaFuncAttributeMaxDynamicSharedMemorySize, 81920);
        attr_done = true;
    }

    fused_kernel   <<<ROWS_TOT / 64, 256, 81920>>>(atom, adj, bond, W);
    s_kernel       <<<B_, 1024>>>();
    epilogue_kernel<<<ROWS_TOT * F_ / 1024, 256>>>(bias, out);
}

// round 9
// speedup vs baseline: 1.2882x; 1.2882x over previous
#include <cuda_runtime.h>
#include <cstdint>

#define B_   16
#define N_   1024
#define M_   12
#define FB_  32
#define F_   128
#define ROWS_TOT (B_ * N_)   // 16384

__device__ float g_p[ROWS_TOT];
__device__ float g_s[ROWS_TOT];

// Register-only asm helpers (explicit dataflow -> safe, no memory semantics)
static __device__ __forceinline__ uint64_t pk2(float x, float y) {
    uint64_t d; asm("mov.b64 %0, {%1, %2};" : "=l"(d) : "f"(x), "f"(y)); return d;
}
static __device__ __forceinline__ uint64_t pkdup(float x) {
    uint64_t d; asm("mov.b64 %0, {%1, %1};" : "=l"(d) : "f"(x)); return d;
}
static __device__ __forceinline__ void fma2(uint64_t& a, uint64_t u, uint64_t v) {
    asm("fma.rn.f32x2 %0, %1, %2, %0;" : "+l"(a) : "l"(u), "l"(v));
}
static __device__ __forceinline__ float2 upk(uint64_t d) {
    float2 f; asm("mov.b64 {%0, %1}, %2;" : "=f"(f.x), "=f"(f.y) : "l"(d)); return f;
}

// ---------------------------------------------------------------------------
// Kernel 1: one THREAD per m-vector (no shuffles, pure C++).
//   384 threads = 32 rows x 12 m. Each thread: 8 independent LDG.128,
//   r = 1/||v||^2 -> smem. First 32 threads fold 12 r's per row into p.
// ---------------------------------------------------------------------------
__global__ __launch_bounds__(384) void bond_kernel(const float* __restrict__ bond) {
    __shared__ float sR[32 * 12];
    int tid = threadIdx.x;
    size_t v = (size_t)blockIdx.x * 384 + tid;     // global m-vector id
    const float* base = bond + v * FB_;

    float4 x[8];
#pragma unroll
    for (int i = 0; i < 8; ++i) x[i] = *(const float4*)(base + (i << 2));

    float s = 0.f;
#pragma unroll
    for (int i = 0; i < 8; ++i)
        s += x[i].x*x[i].x + x[i].y*x[i].y + x[i].z*x[i].z + x[i].w*x[i].w;
    sR[tid] = 1.0f / s;                            // (sqrt(s))^-2 == 1/s
    __syncthreads();

    if (tid < 32) {
        float sum = 0.f, prod = 1.f;
#pragma unroll
        for (int m = 0; m < M_; ++m) {
            float r = sR[tid * M_ + m];
            sum += r; prod *= r;
        }
        float D  = fmaxf(sum, 1e-12f);
        float d2 = D * D, d4 = d2 * d2;
        g_p[blockIdx.x * 32 + tid] = prod / (d4 * d4 * d4);
    }
}

// ---------------------------------------------------------------------------
// Kernel 2: colsum over B, u = max(colsum,eps)/p, s = u / sum_n u
// ---------------------------------------------------------------------------
__global__ void s_kernel() {
    __shared__ float red[32];
    int b = blockIdx.x, n = threadIdx.x;
    int wid = n >> 5, lane = n & 31;

    float cs = 0.f;
#pragma unroll
    for (int bb = 0; bb < B_; ++bb) cs += g_p[bb * N_ + n];
    float u = fmaxf(cs, 1e-12f) / g_p[b * N_ + n];

    float v = u;
#pragma unroll
    for (int off = 16; off; off >>= 1) v += __shfl_xor_sync(0xffffffffu, v, off);
    if (lane == 0) red[wid] = v;
    __syncthreads();
    if (wid == 0) {
        float t = red[lane];
#pragma unroll
        for (int off = 16; off; off >>= 1) t += __shfl_xor_sync(0xffffffffu, t, off);
        if (lane == 0) red[0] = 1.0f / fmaxf(t, 1e-12f);
    }
    __syncthreads();
    g_s[b * N_ + n] = u * red[0];
}

// ---------------------------------------------------------------------------
// Kernel 3: fused gather + mean + scale + GEMM + bias + ReLU
//   256 blocks x 256 threads, 64 rows each. Static smem 48 KB (sA 32 + sW 16).
//   Microtile 8 rows x 4 cols; col-pair packed fma.rn.f32x2.
//   ALL shared traffic through C++ loads (barrier-ordered by the compiler).
// ---------------------------------------------------------------------------
__global__ __launch_bounds__(256) void fused_kernel(
    const float* __restrict__ atom, const int* __restrict__ adj,
    const float* __restrict__ W, const float* __restrict__ bias,
    float* __restrict__ out)
{
    __shared__ float sA[64][F_];       // 32 KB
    __shared__ float sW[32][F_];       // 16 KB

    int tid  = threadIdx.x;
    int wid  = tid >> 5;
    int lane = tid & 31;
    int row0 = blockIdx.x << 6;

    // ---- Build A tile: each warp produces 8 rows (scaled by s) ----
#pragma unroll
    for (int rr = 0; rr < 8; ++rr) {
        int r = (wid << 3) + rr;
        int g = row0 + r;
        int b = g >> 10;
        const float* arow  = atom + ((size_t)g << 7);
        const float* abase = atom + ((size_t)b << 17);
        int myidx = (lane < M_) ? adj[(size_t)g * M_ + lane] : 0;

        float4 self = *(const float4*)(arow + (lane << 2));
        float ax = 0.f, ay = 0.f, az = 0.f, aw = 0.f;
#pragma unroll
        for (int m = 0; m < M_; ++m) {
            int idx = __shfl_sync(0xffffffffu, myidx, m) & (N_ - 1);
            float4 nb = *(const float4*)(abase + ((size_t)idx << 7) + (lane << 2));
            ax += nb.x; ay += nb.y; az += nb.z; aw += nb.w;
        }
        float sc = g_s[g];
        const float inv12 = 1.0f / 12.0f;
        float4 av;
        av.x = (self.x + ax * inv12) * sc;
        av.y = (self.y + ay * inv12) * sc;
        av.z = (self.z + az * inv12) * sc;
        av.w = (self.w + aw * inv12) * sc;
        *(float4*)&sA[r][lane << 2] = av;
    }

    // ---- GEMM: 8 rows x 4 cols per thread, col-pair packed f32x2 ----
    uint64_t acc[8][2];
#pragma unroll
    for (int r = 0; r < 8; ++r) { acc[r][0] = 0ull; acc[r][1] = 0ull; }

#pragma unroll
    for (int kc = 0; kc < 4; ++kc) {
        __syncthreads();               // drain readers of sW (and cover sA build)
        {
            const float4* src = (const float4*)(W + (size_t)(kc << 5) * F_);
            float4* dstw = (float4*)sW;
#pragma unroll
            for (int t = 0; t < 4; ++t) dstw[tid + (t << 8)] = src[tid + (t << 8)];
        }
        __syncthreads();

        int kb = kc << 5;
#pragma unroll
        for (int k4 = 0; k4 < 8; ++k4) {
            float a[8][4];
#pragma unroll
            for (int r = 0; r < 8; ++r)
                *(float4*)a[r] = *(const float4*)&sA[(wid << 3) + r][kb + (k4 << 2)];
#pragma unroll
            for (int q = 0; q < 4; ++q) {
                float4 wv = *(const float4*)&sW[(k4 << 2) + q][lane << 2];
                uint64_t w01 = pk2(wv.x, wv.y);
                uint64_t w23 = pk2(wv.z, wv.w);
#pragma unroll
                for (int r = 0; r < 8; ++r) {
                    uint64_t p = pkdup(a[r][q]);
                    fma2(acc[r][0], p, w01);
                    fma2(acc[r][1], p, w23);
                }
            }
        }
    }

    // ---- Epilogue: bias + ReLU ----
    float4 bv = *(const float4*)(bias + (lane << 2));
#pragma unroll
    for (int r = 0; r < 8; ++r) {
        int g = row0 + (wid << 3) + r;
        float2 lo = upk(acc[r][0]);
        float2 hi = upk(acc[r][1]);
        float4 o;
        o.x = fmaxf(lo.x + bv.x, 0.f);
        o.y = fmaxf(lo.y + bv.y, 0.f);
        o.z = fmaxf(hi.x + bv.z, 0.f);
        o.w = fmaxf(hi.y + bv.w, 0.f);
        *(float4*)(out + ((size_t)g << 7) + (lane << 2)) = o;
    }
}

// ---------------------------------------------------------------------------
extern "C" void kernel_launch(void* const* d_in, const int* in_sizes, int n_in,
                              void* d_out, int out_size) {
    const float* atom = (const float*)d_in[0];
    const float* bond = (const float*)d_in[1];
    const int*   adj  = (const int*)d_in[2];
    const float* W    = (const float*)d_in[3];
    const float* bias = (const float*)d_in[4];
    float*       out  = (float*)d_out;

    bond_kernel <<<ROWS_TOT / 32, 384>>>(bond);
    s_kernel    <<<B_, 1024>>>();
    fused_kernel<<<ROWS_TOT / 64, 256>>>(atom, adj, W, bias, out);
}